// round 6
// baseline (speedup 1.0000x reference)
#include <cuda_runtime.h>
#include <math.h>

#define N_NODES 8192
#define F_DIM   128
#define EPS      1e-7f
#define MAX_TANH (1.0f - 1e-6f)

// Scratch (device globals: no allocation allowed)
__device__ float g_t[N_NODES * F_DIM];      // tangent features after embed stage
__device__ float g_neigh[N_NODES * F_DIM];  // aggregated neighbor features

// ---------------------------------------------------------------------------
// Block-wide sum reduction for 128 threads (4 warps).
// ---------------------------------------------------------------------------
__device__ __forceinline__ float block_reduce_sum_128(float v, float* sbuf) {
    #pragma unroll
    for (int o = 16; o > 0; o >>= 1)
        v += __shfl_down_sync(0xffffffffu, v, o);
    int w = threadIdx.x >> 5;
    if ((threadIdx.x & 31) == 0) sbuf[w] = v;
    __syncthreads();
    if (threadIdx.x < 4) {
        float r = sbuf[threadIdx.x];
        #pragma unroll
        for (int o = 2; o > 0; o >>= 1)
            r += __shfl_down_sync(0x0000000fu, r, o);
        if (threadIdx.x == 0) sbuf[0] = r;
    }
    __syncthreads();
    float r = sbuf[0];
    __syncthreads();   // protect sbuf for next reuse
    return r;
}

// ---------------------------------------------------------------------------
// K1: per row i:
//   u = log0(x);  v = u @ embed;  h = exp0(v);  h = h_add(h, embed_bias);
//   t = log0(h)  -> g_t
// One block (128 threads) per row; thread c owns feature column c.
// ---------------------------------------------------------------------------
__global__ void __launch_bounds__(128)
k1_embed(const float* __restrict__ x,
         const float* __restrict__ embed,
         const float* __restrict__ ebias) {
    const int row = blockIdx.x;
    const int tid = threadIdx.x;
    __shared__ float su[F_DIM];
    __shared__ float sred[4];

    float xi = x[row * F_DIM + tid];

    // u = log0(x)
    float n2 = block_reduce_sum_128(xi * xi, sred);
    float n  = fmaxf(sqrtf(n2), EPS);
    float u  = atanhf(fminf(n, MAX_TANH)) * xi / n;
    su[tid] = u;
    __syncthreads();

    // v = u @ embed  (thread tid computes column tid; embed rows coalesced)
    float v = 0.0f;
    #pragma unroll 8
    for (int k = 0; k < F_DIM; k++)
        v = fmaf(su[k], __ldg(&embed[k * F_DIM + tid]), v);

    // h = exp0(v)
    float vn2 = block_reduce_sum_128(v * v, sred);
    float vn  = fmaxf(sqrtf(vn2), EPS);
    float h   = tanhf(vn) * v / vn;

    // h = h_add(h, bias)
    float b  = __ldg(&ebias[tid]);
    float xy = block_reduce_sum_128(h * b, sred);
    float x2 = block_reduce_sum_128(h * h, sred);
    float y2 = block_reduce_sum_128(b * b, sred);
    float num = (1.0f + 2.0f * xy + y2) * h + (1.0f - x2) * b;
    float den = fmaxf(1.0f + 2.0f * xy + x2 * y2, EPS);
    float h2  = num / den;

    // t = log0(h2)
    float hn2 = block_reduce_sum_128(h2 * h2, sred);
    float hn  = fmaxf(sqrtf(hn2), EPS);
    float t   = atanhf(fminf(hn, MAX_TANH)) * h2 / hn;

    g_t[row * F_DIM + tid] = t;
}

// ---------------------------------------------------------------------------
// K2: neigh = exp0(adj @ g_t), exploiting ~1% sparsity of adj.
// One warp per row. Each lane streams float4 of adj row; ballot compacts
// nonzeros; for each nonzero (j, a) all lanes FMA a * t[j, 4*lane..4*lane+3].
// ---------------------------------------------------------------------------
__global__ void __launch_bounds__(256)
k2_aggregate(const float* __restrict__ adj) {
    const int warp = (blockIdx.x * blockDim.x + threadIdx.x) >> 5;
    const int lane = threadIdx.x & 31;
    if (warp >= N_NODES) return;

    const float4* arow = reinterpret_cast<const float4*>(adj + (size_t)warp * N_NODES);
    const float4* t4   = reinterpret_cast<const float4*>(g_t);

    float a0 = 0.0f, a1 = 0.0f, a2 = 0.0f, a3 = 0.0f;

    #pragma unroll 4
    for (int base = 0; base < N_NODES; base += 128) {
        float4 v = arow[(base >> 2) + lane];   // lane covers cols base+4*lane .. +3

        unsigned m0 = __ballot_sync(0xffffffffu, v.x != 0.0f);
        unsigned m1 = __ballot_sync(0xffffffffu, v.y != 0.0f);
        unsigned m2 = __ballot_sync(0xffffffffu, v.z != 0.0f);
        unsigned m3 = __ballot_sync(0xffffffffu, v.w != 0.0f);

        #define PROC(mask, comp, sub)                                          \
            while (mask) {                                                     \
                int b = __ffs(mask) - 1; mask &= (mask - 1);                   \
                float a = __shfl_sync(0xffffffffu, comp, b);                   \
                int j = base + 4 * b + (sub);                                  \
                float4 tv = __ldg(&t4[j * (F_DIM / 4) + lane]);                \
                a0 = fmaf(a, tv.x, a0);                                        \
                a1 = fmaf(a, tv.y, a1);                                        \
                a2 = fmaf(a, tv.z, a2);                                        \
                a3 = fmaf(a, tv.w, a3);                                        \
            }
        PROC(m0, v.x, 0)
        PROC(m1, v.y, 1)
        PROC(m2, v.z, 2)
        PROC(m3, v.w, 3)
        #undef PROC
    }

    // exp0 of the aggregated row (norm over 128 features)
    float s = a0 * a0 + a1 * a1 + a2 * a2 + a3 * a3;
    #pragma unroll
    for (int o = 16; o > 0; o >>= 1)
        s += __shfl_xor_sync(0xffffffffu, s, o);
    float n  = fmaxf(sqrtf(s), EPS);
    float sc = tanhf(n) / n;

    float4 outv = make_float4(a0 * sc, a1 * sc, a2 * sc, a3 * sc);
    reinterpret_cast<float4*>(g_neigh)[warp * (F_DIM / 4) + lane] = outv;
}

// ---------------------------------------------------------------------------
// K3: z = [x ; neigh] (256-d);  w = log0(z);  o = w @ layer;
//     out = h_add(exp0(o), layer_bias)
// One block (128 threads) per row.
// ---------------------------------------------------------------------------
__global__ void __launch_bounds__(128)
k3_layer(const float* __restrict__ x,
         const float* __restrict__ layer,
         const float* __restrict__ lbias,
         float* __restrict__ out) {
    const int row = blockIdx.x;
    const int tid = threadIdx.x;
    __shared__ float sw[2 * F_DIM];
    __shared__ float sred[4];

    float z0 = x[row * F_DIM + tid];
    float z1 = g_neigh[row * F_DIM + tid];

    // log0 over the concatenated 256-d vector
    float n2 = block_reduce_sum_128(z0 * z0 + z1 * z1, sred);
    float n  = fmaxf(sqrtf(n2), EPS);
    float sc = atanhf(fminf(n, MAX_TANH)) / n;
    sw[tid]         = z0 * sc;
    sw[F_DIM + tid] = z1 * sc;
    __syncthreads();

    // o = w @ layer   (256 x 128)
    float o = 0.0f;
    #pragma unroll 8
    for (int k = 0; k < 2 * F_DIM; k++)
        o = fmaf(sw[k], __ldg(&layer[k * F_DIM + tid]), o);

    // exp0
    float on2 = block_reduce_sum_128(o * o, sred);
    float on  = fmaxf(sqrtf(on2), EPS);
    float e   = tanhf(on) * o / on;

    // h_add with layer_bias
    float b  = __ldg(&lbias[tid]);
    float xy = block_reduce_sum_128(e * b, sred);
    float x2 = block_reduce_sum_128(e * e, sred);
    float y2 = block_reduce_sum_128(b * b, sred);
    float num = (1.0f + 2.0f * xy + y2) * e + (1.0f - x2) * b;
    float den = fmaxf(1.0f + 2.0f * xy + x2 * y2, EPS);

    out[row * F_DIM + tid] = num / den;
}

// ---------------------------------------------------------------------------
extern "C" void kernel_launch(void* const* d_in, const int* in_sizes, int n_in,
                              void* d_out, int out_size) {
    const float* x     = (const float*)d_in[0];   // [8192,128]
    const float* adj   = (const float*)d_in[1];   // [8192,8192]
    const float* embed = (const float*)d_in[2];   // [128,128]
    const float* layer = (const float*)d_in[3];   // [256,128]
    const float* eb    = (const float*)d_in[4];   // [128]
    const float* lb    = (const float*)d_in[5];   // [128]
    float* out = (float*)d_out;                   // [8192,128]

    k1_embed<<<N_NODES, 128>>>(x, embed, eb);

    // one warp per row: 8192 warps -> 1024 blocks of 256 threads
    k2_aggregate<<<(N_NODES * 32) / 256, 256>>>(adj);

    k3_layer<<<N_NODES, 128>>>(x, layer, lb, out);
}

// round 11
// speedup vs baseline: 1.0008x; 1.0008x over previous
#include <cuda_runtime.h>
#include <math.h>

#define N_NODES 8192
#define F_DIM   128
#define EPS      1e-7f
#define MAX_TANH (1.0f - 1e-6f)

// Scratch (device globals: no allocation allowed)
__device__ float g_t[N_NODES * F_DIM];      // tangent features after embed stage
__device__ float g_neigh[N_NODES * F_DIM];  // aggregated neighbor features

// ---------------------------------------------------------------------------
// Block-wide sum reduction for 128 threads (4 warps).
// ---------------------------------------------------------------------------
__device__ __forceinline__ float block_reduce_sum_128(float v, float* sbuf) {
    #pragma unroll
    for (int o = 16; o > 0; o >>= 1)
        v += __shfl_down_sync(0xffffffffu, v, o);
    int w = threadIdx.x >> 5;
    if ((threadIdx.x & 31) == 0) sbuf[w] = v;
    __syncthreads();
    if (threadIdx.x < 4) {
        float r = sbuf[threadIdx.x];
        #pragma unroll
        for (int o = 2; o > 0; o >>= 1)
            r += __shfl_down_sync(0x0000000fu, r, o);
        if (threadIdx.x == 0) sbuf[0] = r;
    }
    __syncthreads();
    float r = sbuf[0];
    __syncthreads();   // protect sbuf for next reuse
    return r;
}

// ---------------------------------------------------------------------------
// K1: per row i:
//   u = log0(x);  v = u @ embed;  h = exp0(v);  h = h_add(h, embed_bias);
//   t = log0(h)  -> g_t
// One block (128 threads) per row; thread c owns feature column c.
// ---------------------------------------------------------------------------
__global__ void __launch_bounds__(128)
k1_embed(const float* __restrict__ x,
         const float* __restrict__ embed,
         const float* __restrict__ ebias) {
    const int row = blockIdx.x;
    const int tid = threadIdx.x;
    __shared__ float su[F_DIM];
    __shared__ float sred[4];

    float xi = x[row * F_DIM + tid];

    // u = log0(x)
    float n2 = block_reduce_sum_128(xi * xi, sred);
    float n  = fmaxf(sqrtf(n2), EPS);
    float u  = atanhf(fminf(n, MAX_TANH)) * xi / n;
    su[tid] = u;
    __syncthreads();

    // v = u @ embed  (thread tid computes column tid; embed rows coalesced)
    float v = 0.0f;
    #pragma unroll 8
    for (int k = 0; k < F_DIM; k++)
        v = fmaf(su[k], __ldg(&embed[k * F_DIM + tid]), v);

    // h = exp0(v)
    float vn2 = block_reduce_sum_128(v * v, sred);
    float vn  = fmaxf(sqrtf(vn2), EPS);
    float h   = tanhf(vn) * v / vn;

    // h = h_add(h, bias)
    float b  = __ldg(&ebias[tid]);
    float xy = block_reduce_sum_128(h * b, sred);
    float x2 = block_reduce_sum_128(h * h, sred);
    float y2 = block_reduce_sum_128(b * b, sred);
    float num = (1.0f + 2.0f * xy + y2) * h + (1.0f - x2) * b;
    float den = fmaxf(1.0f + 2.0f * xy + x2 * y2, EPS);
    float h2  = num / den;

    // t = log0(h2)
    float hn2 = block_reduce_sum_128(h2 * h2, sred);
    float hn  = fmaxf(sqrtf(hn2), EPS);
    float t   = atanhf(fminf(hn, MAX_TANH)) * h2 / hn;

    g_t[row * F_DIM + tid] = t;
}

// ---------------------------------------------------------------------------
// K2: neigh = exp0(adj @ g_t), exploiting ~1% sparsity of adj.
// One warp per row. Each lane streams float4 of adj row; ballot compacts
// nonzeros; for each nonzero (j, a) all lanes FMA a * t[j, 4*lane..4*lane+3].
// ---------------------------------------------------------------------------
__global__ void __launch_bounds__(256)
k2_aggregate(const float* __restrict__ adj) {
    const int warp = (blockIdx.x * blockDim.x + threadIdx.x) >> 5;
    const int lane = threadIdx.x & 31;
    if (warp >= N_NODES) return;

    const float4* arow = reinterpret_cast<const float4*>(adj + (size_t)warp * N_NODES);
    const float4* t4   = reinterpret_cast<const float4*>(g_t);

    float a0 = 0.0f, a1 = 0.0f, a2 = 0.0f, a3 = 0.0f;

    #pragma unroll 4
    for (int base = 0; base < N_NODES; base += 128) {
        float4 v = arow[(base >> 2) + lane];   // lane covers cols base+4*lane .. +3

        unsigned m0 = __ballot_sync(0xffffffffu, v.x != 0.0f);
        unsigned m1 = __ballot_sync(0xffffffffu, v.y != 0.0f);
        unsigned m2 = __ballot_sync(0xffffffffu, v.z != 0.0f);
        unsigned m3 = __ballot_sync(0xffffffffu, v.w != 0.0f);

        #define PROC(mask, comp, sub)                                          \
            while (mask) {                                                     \
                int b = __ffs(mask) - 1; mask &= (mask - 1);                   \
                float a = __shfl_sync(0xffffffffu, comp, b);                   \
                int j = base + 4 * b + (sub);                                  \
                float4 tv = __ldg(&t4[j * (F_DIM / 4) + lane]);                \
                a0 = fmaf(a, tv.x, a0);                                        \
                a1 = fmaf(a, tv.y, a1);                                        \
                a2 = fmaf(a, tv.z, a2);                                        \
                a3 = fmaf(a, tv.w, a3);                                        \
            }
        PROC(m0, v.x, 0)
        PROC(m1, v.y, 1)
        PROC(m2, v.z, 2)
        PROC(m3, v.w, 3)
        #undef PROC
    }

    // exp0 of the aggregated row (norm over 128 features)
    float s = a0 * a0 + a1 * a1 + a2 * a2 + a3 * a3;
    #pragma unroll
    for (int o = 16; o > 0; o >>= 1)
        s += __shfl_xor_sync(0xffffffffu, s, o);
    float n  = fmaxf(sqrtf(s), EPS);
    float sc = tanhf(n) / n;

    float4 outv = make_float4(a0 * sc, a1 * sc, a2 * sc, a3 * sc);
    reinterpret_cast<float4*>(g_neigh)[warp * (F_DIM / 4) + lane] = outv;
}

// ---------------------------------------------------------------------------
// K3: z = [x ; neigh] (256-d);  w = log0(z);  o = w @ layer;
//     out = h_add(exp0(o), layer_bias)
// One block (128 threads) per row.
// ---------------------------------------------------------------------------
__global__ void __launch_bounds__(128)
k3_layer(const float* __restrict__ x,
         const float* __restrict__ layer,
         const float* __restrict__ lbias,
         float* __restrict__ out) {
    const int row = blockIdx.x;
    const int tid = threadIdx.x;
    __shared__ float sw[2 * F_DIM];
    __shared__ float sred[4];

    float z0 = x[row * F_DIM + tid];
    float z1 = g_neigh[row * F_DIM + tid];

    // log0 over the concatenated 256-d vector
    float n2 = block_reduce_sum_128(z0 * z0 + z1 * z1, sred);
    float n  = fmaxf(sqrtf(n2), EPS);
    float sc = atanhf(fminf(n, MAX_TANH)) / n;
    sw[tid]         = z0 * sc;
    sw[F_DIM + tid] = z1 * sc;
    __syncthreads();

    // o = w @ layer   (256 x 128)
    float o = 0.0f;
    #pragma unroll 8
    for (int k = 0; k < 2 * F_DIM; k++)
        o = fmaf(sw[k], __ldg(&layer[k * F_DIM + tid]), o);

    // exp0
    float on2 = block_reduce_sum_128(o * o, sred);
    float on  = fmaxf(sqrtf(on2), EPS);
    float e   = tanhf(on) * o / on;

    // h_add with layer_bias
    float b  = __ldg(&lbias[tid]);
    float xy = block_reduce_sum_128(e * b, sred);
    float x2 = block_reduce_sum_128(e * e, sred);
    float y2 = block_reduce_sum_128(b * b, sred);
    float num = (1.0f + 2.0f * xy + y2) * e + (1.0f - x2) * b;
    float den = fmaxf(1.0f + 2.0f * xy + x2 * y2, EPS);

    out[row * F_DIM + tid] = num / den;
}

// ---------------------------------------------------------------------------
extern "C" void kernel_launch(void* const* d_in, const int* in_sizes, int n_in,
                              void* d_out, int out_size) {
    const float* x     = (const float*)d_in[0];   // [8192,128]
    const float* adj   = (const float*)d_in[1];   // [8192,8192]
    const float* embed = (const float*)d_in[2];   // [128,128]
    const float* layer = (const float*)d_in[3];   // [256,128]
    const float* eb    = (const float*)d_in[4];   // [128]
    const float* lb    = (const float*)d_in[5];   // [128]
    float* out = (float*)d_out;                   // [8192,128]

    k1_embed<<<N_NODES, 128>>>(x, embed, eb);

    // one warp per row: 8192 warps -> 1024 blocks of 256 threads
    k2_aggregate<<<(N_NODES * 32) / 256, 256>>>(adj);

    k3_layer<<<N_NODES, 128>>>(x, layer, lb, out);
}